// round 15
// baseline (speedup 1.0000x reference)
#include <cuda_runtime.h>
#include <cuda_fp16.h>
#include <cstdint>

// x: (8,512,32,32) fp32 == xr[8192][512]; proj_w (512,512); proj_b (512)
// score_w (512); score_b (1); ln_w (25); ln_b (25); out (8,512,28,28) fp32

#define M_ROWS 8192
#define KDIM   512
#define ODIM   512
#define HH     28

// ---------------- scratch ----------------
__device__ float g_proj[M_ROWS * ODIM];     // 16 MB
__device__ float g_wall[8 * 784 * 25];      // softmax weights, 627 KB
__device__ __half g_W[ODIM * KDIM];         // 0.5 MB (fp16(w))

// ---------------- helpers ----------------
__device__ __forceinline__ uint32_t smem_u32(const void* p) {
    uint32_t a;
    asm("{ .reg .u64 t; cvta.to.shared.u64 t, %1; cvt.u32.u64 %0, t; }" : "=r"(a) : "l"(p));
    return a;
}
__device__ __forceinline__ void cp_async16(uint32_t sa, const void* ga) {
    asm volatile("cp.async.cg.shared.global [%0], [%1], 16;" :: "r"(sa), "l"(ga) : "memory");
}
__device__ __forceinline__ void cp_commit() {
    asm volatile("cp.async.commit_group;" ::: "memory");
}
__device__ __forceinline__ void cp_wait1() {
    asm volatile("cp.async.wait_group 1;" ::: "memory");
}
__device__ __forceinline__ void ldsm4(uint32_t* r, uint32_t a) {
    asm volatile("ldmatrix.sync.aligned.m8n8.x4.shared.b16 {%0,%1,%2,%3}, [%4];"
                 : "=r"(r[0]), "=r"(r[1]), "=r"(r[2]), "=r"(r[3]) : "r"(a));
}
__device__ __forceinline__ void mma_f16(float* c, const uint32_t* a, const uint32_t* b) {
    asm volatile(
        "mma.sync.aligned.m16n8k16.row.col.f32.f16.f16.f32 "
        "{%0,%1,%2,%3}, {%4,%5,%6,%7}, {%8,%9}, {%0,%1,%2,%3};"
        : "+f"(c[0]), "+f"(c[1]), "+f"(c[2]), "+f"(c[3])
        : "r"(a[0]), "r"(a[1]), "r"(a[2]), "r"(a[3]), "r"(b[0]), "r"(b[1]));
}
__device__ __forceinline__ uint4 cvt8(float4 a, float4 b) {
    __half2 h0 = __floats2half2_rn(a.x, a.y);
    __half2 h1 = __floats2half2_rn(a.z, a.w);
    __half2 h2 = __floats2half2_rn(b.x, b.y);
    __half2 h3 = __floats2half2_rn(b.z, b.w);
    uint4 u;
    u.x = *(uint32_t*)&h0; u.y = *(uint32_t*)&h1;
    u.z = *(uint32_t*)&h2; u.w = *(uint32_t*)&h3;
    return u;
}

// ---------------- kernel 1: convert proj_w -> g_W fp16 ----------------
__global__ __launch_bounds__(256) void convw_kernel(const float* __restrict__ pw) {
    const int i = blockIdx.x * 256 + threadIdx.x;   // 32768 chunks of 8 floats
    float4 a = ((const float4*)pw)[2 * i];
    float4 b = ((const float4*)pw)[2 * i + 1];
    ((uint4*)g_W)[i] = cvt8(a, b);
}

// ---------------- fused GEMM (in-loader x conversion) + score/weights CTAs ----------------
#define RGN     8192
#define STAGEB  (2 * RGN)
#define NIT     16

__device__ __forceinline__ uint32_t swz64(int r, int q) {
    return (uint32_t)(r * 64 + ((q ^ ((r >> 1) & 3)) << 4));
}

__global__ __launch_bounds__(256, 2) void gemm_fused(const float* __restrict__ x,
                                                     const float* __restrict__ bias,
                                                     const float* __restrict__ ln_w,
                                                     const float* __restrict__ ln_b,
                                                     const float* __restrict__ sw,
                                                     const float* __restrict__ sb) {
    __shared__ __align__(16) char smem[2 * STAGEB];   // 32KB
    const int tid = threadIdx.x;
    const int lane = tid & 31;
    const int wid = tid >> 5;

    // ---- score + weights CTAs (y = 64, 65): one per n ----
    if (blockIdx.y >= 64) {
        float* s_sc = (float*)smem;   // 1024 scores
        const int n = ((int)blockIdx.y - 64) * 4 + (int)blockIdx.x;
        const float* xb = x + (size_t)n * 1024 * KDIM;
        // phase 1: 1024 score dots; each warp 128 rows, 4 at a time
        const float4* w4 = (const float4*)sw;
        float4 w0 = w4[2 * lane],      w1 = w4[2 * lane + 1];
        float4 w2 = w4[2 * lane + 64], w3 = w4[2 * lane + 65];
        const float sbv = sb[0];
        for (int j = 0; j < 32; j++) {
            const int row0 = wid * 128 + j * 4;
            float4 v[4][4];
#pragma unroll
            for (int r = 0; r < 4; r++) {
                const float4* s = (const float4*)(xb + (size_t)(row0 + r) * KDIM);
                v[r][0] = s[2 * lane];
                v[r][1] = s[2 * lane + 1];
                v[r][2] = s[2 * lane + 64];
                v[r][3] = s[2 * lane + 65];
            }
            float acc[4];
#pragma unroll
            for (int r = 0; r < 4; r++) {
                acc[r] = v[r][0].x * w0.x + v[r][0].y * w0.y + v[r][0].z * w0.z + v[r][0].w * w0.w
                       + v[r][1].x * w1.x + v[r][1].y * w1.y + v[r][1].z * w1.z + v[r][1].w * w1.w
                       + v[r][2].x * w2.x + v[r][2].y * w2.y + v[r][2].z * w2.z + v[r][2].w * w2.w
                       + v[r][3].x * w3.x + v[r][3].y * w3.y + v[r][3].z * w3.z + v[r][3].w * w3.w;
            }
#pragma unroll
            for (int off = 16; off; off >>= 1)
#pragma unroll
                for (int r = 0; r < 4; r++)
                    acc[r] += __shfl_xor_sync(0xffffffffu, acc[r], off);
            if (lane == 0) {
#pragma unroll
                for (int r = 0; r < 4; r++) s_sc[row0 + r] = acc[r] + sbv;
            }
        }
        __syncthreads();
        // phase 2: LN + softmax per window
        for (int widx = tid; widx < 784; widx += 256) {
            const int hh = widx / 28;
            const int ww = widx - hh * 28;
            float v[25];
            float mu = 0.f;
#pragma unroll
            for (int ki = 0; ki < 5; ki++)
#pragma unroll
                for (int kj = 0; kj < 5; kj++) {
                    float tv = s_sc[(hh + ki) * 32 + ww + kj];
                    v[ki * 5 + kj] = tv;
                    mu += tv;
                }
            mu *= (1.f / 25.f);
            float var = 0.f;
#pragma unroll
            for (int k = 0; k < 25; k++) {
                float d = v[k] - mu;
                var += d * d;
            }
            var *= (1.f / 25.f);
            float inv = rsqrtf(var + 1e-5f);
            float mx = -1e30f;
#pragma unroll
            for (int k = 0; k < 25; k++) {
                v[k] = (v[k] - mu) * inv * ln_w[k] + ln_b[k];
                mx = fmaxf(mx, v[k]);
            }
            float s = 0.f;
#pragma unroll
            for (int k = 0; k < 25; k++) {
                v[k] = __expf(v[k] - mx);
                s += v[k];
            }
            float r = 1.f / s;
            float* dst = g_wall + (size_t)n * 19600 + widx * 25;
#pragma unroll
            for (int k = 0; k < 25; k++) dst[k] = v[k] * r;
        }
        return;
    }

    // ---- GEMM tile CTAs ----
    const int warpM = wid >> 1;
    const int warpN = wid & 1;
    const int bm = blockIdx.y * 128;
    const int bn = blockIdx.x * 128;
    const uint32_t sbase = smem_u32(smem);

    // A loader: thread -> row = tid>>1, chunks q0, q0+1 (fp32 x, convert on the fly)
    const int arowL = tid >> 1;
    const int q0 = (tid & 1) * 2;
    const float* xrow = x + (size_t)(bm + arowL) * KDIM + q0 * 8;
    const uint32_t stsA0 = sbase + swz64(arowL, q0);
    const uint32_t stsA1 = sbase + swz64(arowL, q0 + 1);

    // W loader: 2 cp.async chunks per thread
    uint32_t ldstW[2];
    const __half* lsrcW[2];
#pragma unroll
    for (int i = 0; i < 2; i++) {
        int cw = tid + 256 * i;
        int r = cw >> 2, q = cw & 3;
        ldstW[i] = sbase + RGN + swz64(r, q);
        lsrcW[i] = g_W + (size_t)(bn + r) * KDIM + q * 8;
    }

    const int t = lane >> 3;
    const int arow0 = warpM * 32 + (t & 1) * 8 + (lane & 7);
    const int brow = warpN * 64 + (t >> 1) * 8 + (lane & 7);
    const int aq = t >> 1;
    const int bq = t & 1;

    float acc[2][8][4];
#pragma unroll
    for (int i = 0; i < 2; i++)
#pragma unroll
        for (int j = 0; j < 8; j++)
#pragma unroll
            for (int q = 0; q < 4; q++) acc[i][j][q] = 0.f;

    // prologue
    float4 xr0, xr1, xr2, xr3;
    {   // stage 0: load, convert, STS
        const float4* s = (const float4*)xrow;
        xr0 = s[0]; xr1 = s[1]; xr2 = s[2]; xr3 = s[3];
        *(uint4*)(smem + (stsA0 - sbase)) = cvt8(xr0, xr1);
        *(uint4*)(smem + (stsA1 - sbase)) = cvt8(xr2, xr3);
    }
#pragma unroll
    for (int i = 0; i < 2; i++) cp_async16(ldstW[i], lsrcW[i]);
    cp_commit();                                   // group W(0)
#pragma unroll
    for (int i = 0; i < 2; i++) cp_async16(ldstW[i] + STAGEB, lsrcW[i] + 32);
    cp_commit();                                   // group W(1)
    {   // load x(1) into regs
        const float4* s = (const float4*)(xrow + 32);
        xr0 = s[0]; xr1 = s[1]; xr2 = s[2]; xr3 = s[3];
    }

    for (int it = 0; it < NIT; it++) {
        cp_wait1();
        __syncthreads();
        const uint32_t stb = sbase + (it & 1) * STAGEB;

        // STS x(it+1) into the other buffer (its A-region is free now)
        if (it + 1 < NIT) {
            const uint32_t ob = ((it + 1) & 1) * STAGEB;
            *(uint4*)(smem + (stsA0 - sbase) + ob) = cvt8(xr0, xr1);
            *(uint4*)(smem + (stsA1 - sbase) + ob) = cvt8(xr2, xr3);
        }
        // LDG x(it+2) into regs
        if (it + 2 < NIT) {
            const float4* s = (const float4*)(xrow + (it + 2) * 32);
            xr0 = s[0]; xr1 = s[1]; xr2 = s[2]; xr3 = s[3];
        }

#pragma unroll
        for (int kk = 0; kk < 2; kk++) {
            uint32_t ah[2][4], bb[2][2][4];
            ldsm4(ah[0], stb + swz64(arow0, kk * 2 + aq));
            ldsm4(ah[1], stb + swz64(arow0 + 16, kk * 2 + aq));
            ldsm4(bb[0][0], stb + RGN + swz64(brow, kk * 2 + bq));
            ldsm4(bb[0][1], stb + RGN + swz64(brow + 16, kk * 2 + bq));
            ldsm4(bb[1][0], stb + RGN + swz64(brow + 32, kk * 2 + bq));
            ldsm4(bb[1][1], stb + RGN + swz64(brow + 48, kk * 2 + bq));
            if (kk == 1) {
                __syncthreads();   // all ldsm of this stage done
                if (it + 2 < NIT) {
#pragma unroll
                    for (int i = 0; i < 2; i++)
                        cp_async16(ldstW[i] + (it & 1) * STAGEB, lsrcW[i] + (it + 2) * 32);
                }
                cp_commit();
            }
#pragma unroll
            for (int h = 0; h < 2; h++)
#pragma unroll
                for (int mt = 0; mt < 2; mt++)
#pragma unroll
                    for (int ntl = 0; ntl < 4; ntl++)
                        mma_f16(acc[mt][h * 4 + ntl], ah[mt], &bb[h][ntl >> 1][(ntl & 1) * 2]);
        }
    }

    // epilogue
#pragma unroll
    for (int nt = 0; nt < 8; nt++) {
        const int c = bn + warpN * 64 + nt * 8 + (lane & 3) * 2;
        float2 bbias = *(const float2*)&bias[c];
#pragma unroll
        for (int mt = 0; mt < 2; mt++) {
            const int r = bm + warpM * 32 + mt * 16 + (lane >> 2);
            float2 o0 = {acc[mt][nt][0] + bbias.x, acc[mt][nt][1] + bbias.y};
            float2 o1 = {acc[mt][nt][2] + bbias.x, acc[mt][nt][3] + bbias.y};
            *(float2*)&g_proj[(size_t)r * ODIM + c] = o0;
            *(float2*)&g_proj[(size_t)(r + 8) * ODIM + c] = o1;
        }
    }
}

// ---------------- window attention (R12 frozen: fp32 sweep, 2 hh rows/block) ----------------
#define WIN_SMEM (6 * 32 * 68 * 4 + 2 * 28 * 25 * 4 + 256)

__global__ __launch_bounds__(256) void window_kernel(float* __restrict__ out) {
    extern __shared__ __align__(16) char wsm[];
    float (*ps)[32][68] = (float (*)[32][68])wsm;
    float (*s_w)[28][25] = (float (*)[28][25])(wsm + 6 * 32 * 68 * 4);

    const int hh0 = blockIdx.x * 2;
    const int n = blockIdx.y;
    const int cbase = blockIdx.z * 256;
    const int tid = threadIdx.x;

    for (int i = tid; i < 350; i += 256) {
        float4 v = ((const float4*)(g_wall + (size_t)n * 19600 + hh0 * 700))[i];
        ((float4*)&s_w[0][0][0])[i] = v;
    }

    const int ww = tid & 31;
    const int cq = tid >> 5;
    const bool act = (ww < HH);
    const int wsrc = act ? ww : 0;

#pragma unroll
    for (int cc = 0; cc < 4; cc++) {
        const int c0 = cbase + cc * 64;
        __syncthreads();
        for (int i = tid; i < 3072; i += 256) {
            int pos = i >> 4;
            int q = i & 15;
            int ki = pos >> 5, w = pos & 31;
            *(float4*)&ps[ki][w][q << 2] =
                *(const float4*)&g_proj[(size_t)((n * 32 + hh0 + ki) * 32 + w) * ODIM + c0 + (q << 2)];
        }
        __syncthreads();
#pragma unroll
        for (int hi = 0; hi < 2; hi++) {
            float wt[25];
#pragma unroll
            for (int k = 0; k < 25; k++) wt[k] = s_w[hi][wsrc][k];
            if (act) {
#pragma unroll
                for (int rep = 0; rep < 2; rep++) {
                    int cq4 = cq + rep * 8;
                    float4 acc = {0.f, 0.f, 0.f, 0.f};
#pragma unroll
                    for (int ki = 0; ki < 5; ki++)
#pragma unroll
                        for (int kj = 0; kj < 5; kj++) {
                            float wv = wt[ki * 5 + kj];
                            float4 p = *(const float4*)&ps[hi + ki][ww + kj][cq4 << 2];
                            acc.x = fmaf(wv, p.x, acc.x);
                            acc.y = fmaf(wv, p.y, acc.y);
                            acc.z = fmaf(wv, p.z, acc.z);
                            acc.w = fmaf(wv, p.w, acc.w);
                        }
                    int c = c0 + (cq4 << 2);
                    size_t ob = ((size_t)(n * 512 + c) * HH + hh0 + hi) * HH + ww;
                    out[ob] = acc.x;
                    out[ob + 784] = acc.y;
                    out[ob + 1568] = acc.z;
                    out[ob + 2352] = acc.w;
                }
            }
        }
    }
}

extern "C" void kernel_launch(void* const* d_in, const int* in_sizes, int n_in,
                              void* d_out, int out_size) {
    const float* x       = (const float*)d_in[0];
    const float* proj_w  = (const float*)d_in[1];
    const float* proj_b  = (const float*)d_in[2];
    const float* score_w = (const float*)d_in[3];
    const float* score_b = (const float*)d_in[4];
    const float* ln_w    = (const float*)d_in[5];
    const float* ln_b    = (const float*)d_in[6];
    float* out = (float*)d_out;

    cudaFuncSetAttribute(window_kernel, cudaFuncAttributeMaxDynamicSharedMemorySize, WIN_SMEM);

    convw_kernel<<<128, 256>>>(proj_w);
    gemm_fused<<<dim3(4, 66), 256>>>(x, proj_b, ln_w, ln_b, score_w, score_b);
    window_kernel<<<dim3(14, 8, 2), 256, WIN_SMEM>>>(out);
}

// round 16
// speedup vs baseline: 1.6535x; 1.6535x over previous
#include <cuda_runtime.h>
#include <cuda_fp16.h>
#include <cstdint>

// x: (8,512,32,32) fp32 == xr[8192][512]; proj_w (512,512); proj_b (512)
// score_w (512); score_b (1); ln_w (25); ln_b (25); out (8,512,28,28) fp32

#define M_ROWS 8192
#define KDIM   512
#define ODIM   512
#define HH     28

// ---------------- scratch ----------------
__device__ float g_proj[M_ROWS * ODIM];     // 16 MB
__device__ float g_score[M_ROWS];
__device__ float g_wall[8 * 784 * 25];      // softmax weights, 627 KB
__device__ __half g_A[M_ROWS * KDIM];       // 8 MB   (fp16(x))
__device__ __half g_W[ODIM * KDIM];         // 0.5 MB (fp16(w))

// ---------------- helpers ----------------
__device__ __forceinline__ uint32_t smem_u32(const void* p) {
    uint32_t a;
    asm("{ .reg .u64 t; cvta.to.shared.u64 t, %1; cvt.u32.u64 %0, t; }" : "=r"(a) : "l"(p));
    return a;
}
__device__ __forceinline__ void cp_async16(uint32_t sa, const void* ga) {
    asm volatile("cp.async.cg.shared.global [%0], [%1], 16;" :: "r"(sa), "l"(ga) : "memory");
}
__device__ __forceinline__ void cp_commit() {
    asm volatile("cp.async.commit_group;" ::: "memory");
}
__device__ __forceinline__ void cp_wait1() {
    asm volatile("cp.async.wait_group 1;" ::: "memory");
}
__device__ __forceinline__ void ldsm4(uint32_t* r, uint32_t a) {
    asm volatile("ldmatrix.sync.aligned.m8n8.x4.shared.b16 {%0,%1,%2,%3}, [%4];"
                 : "=r"(r[0]), "=r"(r[1]), "=r"(r[2]), "=r"(r[3]) : "r"(a));
}
__device__ __forceinline__ void mma_f16(float* c, const uint32_t* a, const uint32_t* b) {
    asm volatile(
        "mma.sync.aligned.m16n8k16.row.col.f32.f16.f16.f32 "
        "{%0,%1,%2,%3}, {%4,%5,%6,%7}, {%8,%9}, {%0,%1,%2,%3};"
        : "+f"(c[0]), "+f"(c[1]), "+f"(c[2]), "+f"(c[3])
        : "r"(a[0]), "r"(a[1]), "r"(a[2]), "r"(a[3]), "r"(b[0]), "r"(b[1]));
}
__device__ __forceinline__ uint2 cvt4(float4 a) {
    __half2 h0 = __floats2half2_rn(a.x, a.y);
    __half2 h1 = __floats2half2_rn(a.z, a.w);
    uint2 u;
    u.x = *(uint32_t*)&h0;
    u.y = *(uint32_t*)&h1;
    return u;
}

// ---------------- convert + score (4 rows/warp, MLP 16, contiguous LDG) ----------------
__global__ __launch_bounds__(256) void convert_kernel(const float* __restrict__ x,
                                                      const float* __restrict__ pw,
                                                      const float* __restrict__ sw,
                                                      const float* __restrict__ sb) {
    const int warp = blockIdx.x * 8 + (threadIdx.x >> 5);
    const int lane = threadIdx.x & 31;
    const int row0 = warp * 4;                 // 4 consecutive rows; 8192 % 4 == 0
    const bool isX = row0 < M_ROWS;
    const float* base = isX ? x + (size_t)row0 * KDIM
                            : pw + (size_t)(row0 - M_ROWS) * KDIM;

    // 16 independent contiguous loads (warp covers 512B per LDG, all sectors used)
    float4 v[4][4];
#pragma unroll
    for (int r = 0; r < 4; r++) {
        const float4* s = (const float4*)(base + (size_t)r * KDIM);
#pragma unroll
        for (int k = 0; k < 4; k++) v[r][k] = s[lane + 32 * k];
    }

    __half* dbase = isX ? g_A + (size_t)row0 * KDIM
                        : g_W + (size_t)(row0 - M_ROWS) * KDIM;
#pragma unroll
    for (int r = 0; r < 4; r++) {
        uint2* d = (uint2*)(dbase + (size_t)r * KDIM);
#pragma unroll
        for (int k = 0; k < 4; k++) d[lane + 32 * k] = cvt4(v[r][k]);
    }

    if (isX) {
        const float4* w4 = (const float4*)sw;
        float4 w[4];
#pragma unroll
        for (int k = 0; k < 4; k++) w[k] = w4[lane + 32 * k];
        float acc[4];
#pragma unroll
        for (int r = 0; r < 4; r++) {
            acc[r] = 0.f;
#pragma unroll
            for (int k = 0; k < 4; k++)
                acc[r] += v[r][k].x * w[k].x + v[r][k].y * w[k].y
                        + v[r][k].z * w[k].z + v[r][k].w * w[k].w;
        }
#pragma unroll
        for (int off = 16; off; off >>= 1) {
#pragma unroll
            for (int r = 0; r < 4; r++)
                acc[r] += __shfl_xor_sync(0xffffffffu, acc[r], off);
        }
        if (lane == 0) {
            float sbv = sb[0];
#pragma unroll
            for (int r = 0; r < 4; r++) g_score[row0 + r] = acc[r] + sbv;
        }
    }
}

// ---------------- HMMA GEMM + piggybacked weight blocks (R14, unchanged) ----------------
#define RGN     8192
#define STAGEB  (2 * RGN)
#define NIT     16

__device__ __forceinline__ uint32_t swz64(int r, int q) {
    return (uint32_t)(r * 64 + ((q ^ ((r >> 1) & 3)) << 4));
}

__global__ __launch_bounds__(256, 2) void gemm_mma(const float* __restrict__ bias,
                                                   const float* __restrict__ ln_w,
                                                   const float* __restrict__ ln_b) {
    __shared__ __align__(16) char smem[2 * STAGEB];   // 32KB

    // ---- weights blocks (y = 64, 65): LN + softmax for all windows of one n ----
    if (blockIdx.y >= 64) {
        const int n = ((int)blockIdx.y - 64) * 4 + (int)blockIdx.x;
        for (int widx = threadIdx.x; widx < 784; widx += 256) {
            const int hh = widx / 28;
            const int ww = widx - hh * 28;
            float v[25];
            float mu = 0.f;
#pragma unroll
            for (int ki = 0; ki < 5; ki++)
#pragma unroll
                for (int kj = 0; kj < 5; kj++) {
                    float tv = g_score[(size_t)n * 1024 + (hh + ki) * 32 + ww + kj];
                    v[ki * 5 + kj] = tv;
                    mu += tv;
                }
            mu *= (1.f / 25.f);
            float var = 0.f;
#pragma unroll
            for (int k = 0; k < 25; k++) {
                float d = v[k] - mu;
                var += d * d;
            }
            var *= (1.f / 25.f);
            float inv = rsqrtf(var + 1e-5f);
            float mx = -1e30f;
#pragma unroll
            for (int k = 0; k < 25; k++) {
                v[k] = (v[k] - mu) * inv * ln_w[k] + ln_b[k];
                mx = fmaxf(mx, v[k]);
            }
            float s = 0.f;
#pragma unroll
            for (int k = 0; k < 25; k++) {
                v[k] = __expf(v[k] - mx);
                s += v[k];
            }
            float r = 1.f / s;
            float* dst = g_wall + (size_t)n * 19600 + widx * 25;
#pragma unroll
            for (int k = 0; k < 25; k++) dst[k] = v[k] * r;
        }
        return;
    }

    // ---- GEMM tile blocks ----
    const int tid = threadIdx.x;
    const int lane = tid & 31;
    const int wid = tid >> 5;
    const int warpM = wid >> 1;
    const int warpN = wid & 1;
    const int bm = blockIdx.y * 128;
    const int bn = blockIdx.x * 128;
    const uint32_t sbase = smem_u32(smem);

    uint32_t ldst[4];
    const __half* lsrc[4];
#pragma unroll
    for (int i = 0; i < 4; i++) {
        int c = tid + 256 * i;
        int region = c >> 9;
        int r = (c & 511) >> 2;
        int q = c & 3;
        ldst[i] = sbase + region * RGN + swz64(r, q);
        const __half* base = (region == 0) ? g_A + (size_t)(bm + r) * KDIM
                                           : g_W + (size_t)(bn + r) * KDIM;
        lsrc[i] = base + q * 8;
    }

    const int t = lane >> 3;
    const int arow0 = warpM * 32 + (t & 1) * 8 + (lane & 7);
    const int brow = warpN * 64 + (t >> 1) * 8 + (lane & 7);
    const int aq = t >> 1;
    const int bq = t & 1;

    float acc[2][8][4];
#pragma unroll
    for (int i = 0; i < 2; i++)
#pragma unroll
        for (int j = 0; j < 8; j++)
#pragma unroll
            for (int q = 0; q < 4; q++) acc[i][j][q] = 0.f;

#pragma unroll
    for (int s = 0; s < 2; s++) {
#pragma unroll
        for (int i = 0; i < 4; i++) cp_async16(ldst[i] + s * STAGEB, lsrc[i] + s * 32);
        cp_commit();
    }

    for (int it = 0; it < NIT; it++) {
        cp_wait1();
        __syncthreads();
        const uint32_t stb = sbase + (it & 1) * STAGEB;

#pragma unroll
        for (int kk = 0; kk < 2; kk++) {
            uint32_t ah[2][4], bb[2][2][4];
            ldsm4(ah[0], stb + swz64(arow0, kk * 2 + aq));
            ldsm4(ah[1], stb + swz64(arow0 + 16, kk * 2 + aq));
            ldsm4(bb[0][0], stb + RGN + swz64(brow, kk * 2 + bq));
            ldsm4(bb[0][1], stb + RGN + swz64(brow + 16, kk * 2 + bq));
            ldsm4(bb[1][0], stb + RGN + swz64(brow + 32, kk * 2 + bq));
            ldsm4(bb[1][1], stb + RGN + swz64(brow + 48, kk * 2 + bq));
            if (kk == 1) {
                __syncthreads();
                if (it + 2 < NIT) {
#pragma unroll
                    for (int i = 0; i < 4; i++)
                        cp_async16(ldst[i] + (it & 1) * STAGEB, lsrc[i] + (it + 2) * 32);
                }
                cp_commit();
            }
#pragma unroll
            for (int h = 0; h < 2; h++)
#pragma unroll
                for (int mt = 0; mt < 2; mt++)
#pragma unroll
                    for (int ntl = 0; ntl < 4; ntl++)
                        mma_f16(acc[mt][h * 4 + ntl], ah[mt], &bb[h][ntl >> 1][(ntl & 1) * 2]);
        }
    }

#pragma unroll
    for (int nt = 0; nt < 8; nt++) {
        const int c = bn + warpN * 64 + nt * 8 + (lane & 3) * 2;
        float2 bbias = *(const float2*)&bias[c];
#pragma unroll
        for (int mt = 0; mt < 2; mt++) {
            const int r = bm + warpM * 32 + mt * 16 + (lane >> 2);
            float2 o0 = {acc[mt][nt][0] + bbias.x, acc[mt][nt][1] + bbias.y};
            float2 o1 = {acc[mt][nt][2] + bbias.x, acc[mt][nt][3] + bbias.y};
            *(float2*)&g_proj[(size_t)r * ODIM + c] = o0;
            *(float2*)&g_proj[(size_t)(r + 8) * ODIM + c] = o1;
        }
    }
}

// ---------------- window attention (R12 inner sweep frozen; z-split 4) ----------------
// grid (14, 8, 4): block = (hh pair, n, channel-quarter). 256 threads, 2 chunks of 64ch.
#define WIN_SMEM (6 * 32 * 68 * 4 + 2 * 28 * 25 * 4 + 256)

__global__ __launch_bounds__(256) void window_kernel(float* __restrict__ out) {
    extern __shared__ __align__(16) char wsm[];
    float (*ps)[32][68] = (float (*)[32][68])wsm;                  // [6][32][68]
    float (*s_w)[28][25] = (float (*)[28][25])(wsm + 6 * 32 * 68 * 4);  // [2][28][25]

    const int hh0 = blockIdx.x * 2;
    const int n = blockIdx.y;
    const int cbase = blockIdx.z * 128;
    const int tid = threadIdx.x;

    for (int i = tid; i < 350; i += 256) {
        float4 v = ((const float4*)(g_wall + (size_t)n * 19600 + hh0 * 700))[i];
        ((float4*)&s_w[0][0][0])[i] = v;
    }

    const int ww = tid & 31;
    const int cq = tid >> 5;
    const bool act = (ww < HH);
    const int wsrc = act ? ww : 0;

#pragma unroll
    for (int cc = 0; cc < 2; cc++) {
        const int c0 = cbase + cc * 64;
        __syncthreads();
        // stage 6 rows x 32 w x 64 ch = 3072 float4
        for (int i = tid; i < 3072; i += 256) {
            int pos = i >> 4;
            int q = i & 15;
            int ki = pos >> 5, w = pos & 31;
            *(float4*)&ps[ki][w][q << 2] =
                *(const float4*)&g_proj[(size_t)((n * 32 + hh0 + ki) * 32 + w) * ODIM + c0 + (q << 2)];
        }
        __syncthreads();
#pragma unroll
        for (int hi = 0; hi < 2; hi++) {
            float wt[25];
#pragma unroll
            for (int k = 0; k < 25; k++) wt[k] = s_w[hi][wsrc][k];
            if (act) {
#pragma unroll
                for (int rep = 0; rep < 2; rep++) {
                    int cq4 = cq + rep * 8;
                    float4 acc = {0.f, 0.f, 0.f, 0.f};
#pragma unroll
                    for (int ki = 0; ki < 5; ki++)
#pragma unroll
                        for (int kj = 0; kj < 5; kj++) {
                            float wv = wt[ki * 5 + kj];
                            float4 p = *(const float4*)&ps[hi + ki][ww + kj][cq4 << 2];
                            acc.x = fmaf(wv, p.x, acc.x);
                            acc.y = fmaf(wv, p.y, acc.y);
                            acc.z = fmaf(wv, p.z, acc.z);
                            acc.w = fmaf(wv, p.w, acc.w);
                        }
                    int c = c0 + (cq4 << 2);
                    size_t ob = ((size_t)(n * 512 + c) * HH + hh0 + hi) * HH + ww;
                    out[ob] = acc.x;
                    out[ob + 784] = acc.y;
                    out[ob + 1568] = acc.z;
                    out[ob + 2352] = acc.w;
                }
            }
        }
    }
}

extern "C" void kernel_launch(void* const* d_in, const int* in_sizes, int n_in,
                              void* d_out, int out_size) {
    const float* x       = (const float*)d_in[0];
    const float* proj_w  = (const float*)d_in[1];
    const float* proj_b  = (const float*)d_in[2];
    const float* score_w = (const float*)d_in[3];
    const float* score_b = (const float*)d_in[4];
    const float* ln_w    = (const float*)d_in[5];
    const float* ln_b    = (const float*)d_in[6];
    float* out = (float*)d_out;

    cudaFuncSetAttribute(window_kernel, cudaFuncAttributeMaxDynamicSharedMemorySize, WIN_SMEM);

    convert_kernel<<<272, 256>>>(x, proj_w, score_w, score_b);
    gemm_mma<<<dim3(4, 66), 256>>>(proj_b, ln_w, ln_b);
    window_kernel<<<dim3(14, 8, 4), 256, WIN_SMEM>>>(out);
}